// round 8
// baseline (speedup 1.0000x reference)
#include <cuda_runtime.h>

#define NT 512

// B=256, T=16, O=32, E=32, I=32, H=HL=64, TE=512, EI=64, P=496
// One CTA processes TWO batches (grid=128), interleaved for ILP. 16 warps, occ 1.

struct Params {
    const float* z;
    const float *ee1_w,*ee1_b,*ee2_w,*ee2_b,*ee3_w,*ee3_b;
    const float *ne1_w,*ne1_b,*ne2_w,*ne2_b,*ne3_w,*ne3_b,*ne4_w,*ne4_b;
    const float *le1_w,*le1_b,*le2_w,*le2_b,*le3_w,*le3_b;
    const float *lt1_w,*lt1_b,*lt2_w,*lt2_b,*lt3_w,*lt3_b,*lt4_w,*lt4_b,*lt5_w,*lt5_b;
    float* out;
    int t_future;
};

__device__ __forceinline__ void fma4(float acc[4], float a, const float4& w) {
    acc[0] = fmaf(a, w.x, acc[0]);
    acc[1] = fmaf(a, w.y, acc[1]);
    acc[2] = fmaf(a, w.z, acc[2]);
    acc[3] = fmaf(a, w.w, acc[3]);
}

// two-batch 32x64 layer: outX (opt +=) = inX[32][IN] @ W[IN][64] (+bias) (opt relu)
// 512 threads: 1 row x 4 cols per thread per batch; W loads shared.
template<int IN, bool ACC, bool RELU>
__device__ __forceinline__ void layer2(const float* __restrict__ in0,
                                       const float* __restrict__ in1,
                                       const float* __restrict__ W,
                                       const float* __restrict__ bias,
                                       float* __restrict__ out0,
                                       float* __restrict__ out1, int tid)
{
    const int c0 = (tid & 15) * 4;
    const int r  = tid >> 4;           // 0..31
    float acc[2][4];
    if (ACC) {
#pragma unroll
        for (int j = 0; j < 4; j++) {
            acc[0][j] = out0[r * 64 + c0 + j];
            acc[1][j] = out1[r * 64 + c0 + j];
        }
    } else {
#pragma unroll
        for (int j = 0; j < 4; j++) {
            float bv = bias ? bias[c0 + j] : 0.f;
            acc[0][j] = bv; acc[1][j] = bv;
        }
    }
    const float* i0 = in0 + r * IN;
    const float* i1 = in1 + r * IN;
#pragma unroll 4
    for (int k = 0; k < IN; k += 4) {
        float4 w0 = *(const float4*)(W + (k + 0) * 64 + c0);
        float4 w1 = *(const float4*)(W + (k + 1) * 64 + c0);
        float4 w2 = *(const float4*)(W + (k + 2) * 64 + c0);
        float4 w3 = *(const float4*)(W + (k + 3) * 64 + c0);
        float4 a;
        a = *(const float4*)(i0 + k);
        fma4(acc[0], a.x, w0); fma4(acc[0], a.y, w1); fma4(acc[0], a.z, w2); fma4(acc[0], a.w, w3);
        a = *(const float4*)(i1 + k);
        fma4(acc[1], a.x, w0); fma4(acc[1], a.y, w1); fma4(acc[1], a.z, w2); fma4(acc[1], a.w, w3);
    }
#pragma unroll
    for (int j = 0; j < 4; j++) {
        float v0 = acc[0][j], v1 = acc[1][j];
        if (RELU) { v0 = fmaxf(v0, 0.f); v1 = fmaxf(v1, 0.f); }
        out0[r * 64 + c0 + j] = v0;
        out1[r * 64 + c0 + j] = v1;
    }
}

#define H2S 68   // padded h2 stride

// two-batch 64x64x64 gemm: h2X[64][H2S] = relu(h1X[64][64] @ Ws[64][64] + b2)
// 512 threads: 2 rows x 4 cols per thread per batch; Ws in smem, loads shared.
__device__ __forceinline__ void gemm64_2(const float* __restrict__ A0,
                                         const float* __restrict__ A1,
                                         const float* __restrict__ Ws,
                                         const float* __restrict__ b2,
                                         float* __restrict__ C0,
                                         float* __restrict__ C1, int tid)
{
    const int c0 = (tid & 15) * 4;
    const int r0 = (tid >> 4) * 2;     // 0..62
    float acc[2][2][4];
#pragma unroll
    for (int j = 0; j < 4; j++) {
        float bv = b2[c0 + j];
        acc[0][0][j] = bv; acc[0][1][j] = bv;
        acc[1][0][j] = bv; acc[1][1][j] = bv;
    }
#pragma unroll 2
    for (int k = 0; k < 64; k += 4) {
        float4 w0 = *(const float4*)(Ws + (k + 0) * 64 + c0);
        float4 w1 = *(const float4*)(Ws + (k + 1) * 64 + c0);
        float4 w2 = *(const float4*)(Ws + (k + 2) * 64 + c0);
        float4 w3 = *(const float4*)(Ws + (k + 3) * 64 + c0);
#pragma unroll
        for (int i = 0; i < 2; i++) {
            float4 a = *(const float4*)(A0 + (r0 + i) * 64 + k);
            fma4(acc[0][i], a.x, w0); fma4(acc[0][i], a.y, w1);
            fma4(acc[0][i], a.z, w2); fma4(acc[0][i], a.w, w3);
            float4 b = *(const float4*)(A1 + (r0 + i) * 64 + k);
            fma4(acc[1][i], b.x, w0); fma4(acc[1][i], b.y, w1);
            fma4(acc[1][i], b.z, w2); fma4(acc[1][i], b.w, w3);
        }
    }
#pragma unroll
    for (int i = 0; i < 2; i++)
#pragma unroll
        for (int j = 0; j < 4; j++) {
            C0[(r0 + i) * H2S + c0 + j] = fmaxf(acc[0][i][j], 0.f);
            C1[(r0 + i) * H2S + c0 + j] = fmaxf(acc[1][i][j], 0.f);
        }
}

// two-batch agg: aggX[32][64] = GX[32][64] @ Ws3[64][64] + (31-2n)*b3
__device__ __forceinline__ void aggGemm_2(const float* __restrict__ G0,
                                          const float* __restrict__ G1,
                                          const float* __restrict__ Ws3,
                                          const float* __restrict__ b3,
                                          float* __restrict__ agg0,
                                          float* __restrict__ agg1, int tid)
{
    const int c0 = (tid & 15) * 4;
    const int r  = tid >> 4;
    const float sc = (float)(31 - 2 * r);
    float acc[2][4];
#pragma unroll
    for (int j = 0; j < 4; j++) {
        float bv = sc * b3[c0 + j];
        acc[0][j] = bv; acc[1][j] = bv;
    }
    const float* g0 = G0 + r * 64;
    const float* g1 = G1 + r * 64;
#pragma unroll 4
    for (int k = 0; k < 64; k += 4) {
        float4 w0 = *(const float4*)(Ws3 + (k + 0) * 64 + c0);
        float4 w1 = *(const float4*)(Ws3 + (k + 1) * 64 + c0);
        float4 w2 = *(const float4*)(Ws3 + (k + 2) * 64 + c0);
        float4 w3 = *(const float4*)(Ws3 + (k + 3) * 64 + c0);
        float4 a;
        a = *(const float4*)(g0 + k);
        fma4(acc[0], a.x, w0); fma4(acc[0], a.y, w1); fma4(acc[0], a.z, w2); fma4(acc[0], a.w, w3);
        a = *(const float4*)(g1 + k);
        fma4(acc[1], a.x, w0); fma4(acc[1], a.y, w1); fma4(acc[1], a.z, w2); fma4(acc[1], a.w, w3);
    }
#pragma unroll
    for (int j = 0; j < 4; j++) {
        agg0[r * 64 + c0 + j] = acc[0][j];
        agg1[r * 64 + c0 + j] = acc[1][j];
    }
}

// two-batch small layer: outX[32][OUT] = relu?(inX[32][IN] @ W + b); W loads shared
__device__ __forceinline__ void layer_small_2(const float* __restrict__ in0,
                                              const float* __restrict__ in1, int IN,
                                              const float* __restrict__ W,
                                              const float* __restrict__ bias,
                                              float* __restrict__ out0,
                                              float* __restrict__ out1, int OUT,
                                              bool relu, int tid)
{
    for (int idx = tid; idx < 32 * OUT; idx += NT) {
        int r = idx / OUT, c = idx % OUT;
        float a0 = bias[c], a1 = a0;
        const float* i0 = in0 + r * IN;
        const float* i1 = in1 + r * IN;
#pragma unroll 4
        for (int k = 0; k < IN; k++) {
            float w = W[k * OUT + c];
            a0 = fmaf(i0[k], w, a0);
            a1 = fmaf(i1[k], w, a1);
        }
        out0[idx] = relu ? fmaxf(a0, 0.f) : a0;
        out1[idx] = relu ? fmaxf(a1, 0.f) : a1;
    }
}

// two-batch streamed k-chunk accumulate (1 row x 4 cols per batch):
// acc[bb][col] += sX[row][64] @ Wg[64][64]
__device__ __forceinline__ void acc_chunk2(const float* __restrict__ s0,
                                           const float* __restrict__ s1,
                                           const float* __restrict__ Wg,
                                           float acc[2][4], int r, int c0)
{
    const float* a0 = s0 + r * 64;
    const float* a1 = s1 + r * 64;
#pragma unroll 4
    for (int k = 0; k < 64; k += 4) {
        float4 w0 = *(const float4*)(Wg + (k + 0) * 64 + c0);
        float4 w1 = *(const float4*)(Wg + (k + 1) * 64 + c0);
        float4 w2 = *(const float4*)(Wg + (k + 2) * 64 + c0);
        float4 w3 = *(const float4*)(Wg + (k + 3) * 64 + c0);
        float4 a;
        a = *(const float4*)(a0 + k);
        fma4(acc[0], a.x, w0); fma4(acc[0], a.y, w1); fma4(acc[0], a.z, w2); fma4(acc[0], a.w, w3);
        a = *(const float4*)(a1 + k);
        fma4(acc[1], a.x, w0); fma4(acc[1], a.y, w1); fma4(acc[1], a.z, w2); fma4(acc[1], a.w, w3);
    }
}

// two-batch edge block. b1 pre-folded into ya. W2/W3 in smem.
__device__ __forceinline__ void edge_block_2(const float* ya0, const float* ya1,
                                             const float* yb0, const float* yb1,
                                             const float* Ws2, const float* __restrict__ b2,
                                             const float* Ws3, const float* __restrict__ b3,
                                             float* h1_0, float* h1_1,
                                             float* h2_0, float* h2_1,
                                             float* Gs0, float* Gs1,
                                             float* agg0, float* agg1,
                                             const unsigned char* ii, const unsigned char* jj,
                                             const unsigned short* jl, int tid)
{
    const int n   = tid >> 4;          // 0..31
    const int c0s = (tid & 15) * 4;
    const int rs    = n * 31 - ((n * (n - 1)) >> 1);
    const int iiend = rs + 31 - n;
    float g[2][4];
#pragma unroll
    for (int j = 0; j < 4; j++) { g[0][j] = 0.f; g[1][j] = 0.f; }
    int kcur = 0;

#pragma unroll 1
    for (int ch = 0; ch < 8; ch++) {
        const int p0 = ch * 64;
        // h1 = relu(ya[ii] + yb[jj]) (bias pre-folded into ya)
        for (int e = tid; e < 64 * 64; e += NT) {
            int pl = e >> 6, c = e & 63;
            int p = p0 + pl;
            int ia = ii[p] * 64 + c, ja = jj[p] * 64 + c;
            h1_0[e] = fmaxf(ya0[ia] + yb0[ja], 0.f);
            h1_1[e] = fmaxf(ya1[ia] + yb1[ja], 0.f);
        }
        __syncthreads();
        gemm64_2(h1_0, h1_1, Ws2, b2, h2_0, h2_1, tid);
        __syncthreads();
        // signed sparse scatter into register G (both batches)
        int lo = max(rs, p0), hi = min(iiend, p0 + 64);
        for (int p = lo; p < hi; p++) {
            float4 u = *(const float4*)(h2_0 + (p - p0) * H2S + c0s);
            float4 v = *(const float4*)(h2_1 + (p - p0) * H2S + c0s);
            g[0][0] += u.x; g[0][1] += u.y; g[0][2] += u.z; g[0][3] += u.w;
            g[1][0] += v.x; g[1][1] += v.y; g[1][2] += v.z; g[1][3] += v.w;
        }
        while (kcur < n) {
            int p = jl[(n << 5) + kcur];
            if (p >= p0 + 64) break;
            float4 u = *(const float4*)(h2_0 + (p - p0) * H2S + c0s);
            float4 v = *(const float4*)(h2_1 + (p - p0) * H2S + c0s);
            g[0][0] -= u.x; g[0][1] -= u.y; g[0][2] -= u.z; g[0][3] -= u.w;
            g[1][0] -= v.x; g[1][1] -= v.y; g[1][2] -= v.z; g[1][3] -= v.w;
            kcur++;
        }
    }
#pragma unroll
    for (int j = 0; j < 4; j++) {
        Gs0[n * 64 + c0s + j] = g[0][j];
        Gs1[n * 64 + c0s + j] = g[1][j];
    }
    __syncthreads();
    aggGemm_2(Gs0, Gs1, Ws3, b3, agg0, agg1, tid);
    __syncthreads();
}

// smem layout (float offsets); two batches where doubled
#define OFF_H1    0        // 2 x 64*64
#define OFF_H2    8192     // 2 x 64*68
#define OFF_YA    16896    // 2 x 32*64
#define OFF_YB    20992
#define OFF_AGG   25088
#define OFF_ZC    29184
#define OFF_W2    33280    // 64*64
#define OFF_W3    37376    // 64*64
#define OFF_WLE1  41472    // 128*64
#define SMEM_FLOATS 49664
#define SMEM_BYTES  (SMEM_FLOATS * 4 + 2048 + 1024)

__global__ void __launch_bounds__(NT, 1)
RelationalLatentDynamics_82849919140105_kernel(Params P)
{
    extern __shared__ float sm[];
    float* h1_0 = sm + OFF_H1;       float* h1_1 = h1_0 + 4096;
    float* h2_0 = sm + OFF_H2;       float* h2_1 = h2_0 + 4352;
    float* ya0  = sm + OFF_YA;       float* ya1  = ya0 + 2048;
    float* yb0  = sm + OFF_YB;       float* yb1  = yb0 + 2048;
    float* agg0 = sm + OFF_AGG;      float* agg1 = agg0 + 2048;
    float* zc0  = sm + OFF_ZC;       float* zc1  = zc0 + 2048;
    float* s_w2   = sm + OFF_W2;
    float* s_w3   = sm + OFF_W3;
    float* s_wle1 = sm + OFF_WLE1;
    unsigned short* s_jl = (unsigned short*)(sm + SMEM_FLOATS);
    unsigned char*  s_ii = (unsigned char*)(s_jl + 1024);
    unsigned char*  s_jj = s_ii + 512;

    const int tid = threadIdx.x;
    const int c0 = (tid & 15) * 4;
    const int r  = tid >> 4;

    // pair index tables (padded to 512)
    for (int p = tid; p < 512; p += NT) {
        if (p < 496) {
            int pp = p, i = 0;
            while (pp >= 31 - i) { pp -= 31 - i; i++; }
            s_ii[p] = (unsigned char)i;
            s_jj[p] = (unsigned char)(i + 1 + pp);
        } else {
            s_ii[p] = 0; s_jj[p] = 1;
        }
    }
    for (int idx = tid; idx < 1024; idx += NT) {
        int n = idx >> 5, k = idx & 31;
        s_jl[idx] = (k < n)
            ? (unsigned short)(k * 31 - ((k * (k - 1)) >> 1) + (n - k - 1))
            : (unsigned short)0xFFFF;
    }
    // stage ee2/ee3 and le1 weights
    for (int idx = tid; idx < 4096; idx += NT) {
        s_w2[idx] = P.ee2_w[idx];
        s_w3[idx] = P.ee3_w[idx];
    }
    for (int idx = tid; idx < 8192; idx += NT) s_wle1[idx] = P.le1_w[idx];

    const float* zb0 = P.z + (size_t)(2 * blockIdx.x) * (16 * 32 * 32);
    const float* zb1 = zb0 + 16 * 32 * 32;

    // ---- Phase A: yaX/ybX = srcX @ ee1_w (streamed, register acc; b1 folded into ya) ----
    {
        float accA[2][4], accB[2][4];
#pragma unroll
        for (int j = 0; j < 4; j++) {
            float bv = P.ee1_b[c0 + j];
            accA[0][j] = bv; accA[1][j] = bv;
            accB[0][j] = 0.f; accB[1][j] = 0.f;
        }
#pragma unroll 1
        for (int ch = 0; ch < 8; ch++) {
            for (int idx = tid; idx < 2048; idx += NT) {
                int o = idx >> 6, fl = idx & 63;
                int t = 2 * ch + (fl >> 5), e = fl & 31;
                int off = (t * 32 + o) * 32 + e;
                float v0 = zb0[off], v1 = zb1[off];
                if (t > 0) {
                    int om = off - 1024;
                    v0 -= zb0[om]; v1 -= zb1[om];
                }
                h1_0[o * 64 + fl] = v0;
                h1_1[o * 64 + fl] = v1;
            }
            __syncthreads();
            acc_chunk2(h1_0, h1_1, P.ee1_w + ch * 4096, accA, r, c0);
            acc_chunk2(h1_0, h1_1, P.ee1_w + 512 * 64 + ch * 4096, accB, r, c0);
            __syncthreads();
        }
#pragma unroll
        for (int j = 0; j < 4; j++) {
            ya0[r * 64 + c0 + j] = accA[0][j];
            ya1[r * 64 + c0 + j] = accA[1][j];
            yb0[r * 64 + c0 + j] = accB[0][j];
            yb1[r * 64 + c0 + j] = accB[1][j];
        }
    }
    __syncthreads();

    // ---- ee edge block ----
    edge_block_2(ya0, ya1, yb0, yb1, s_w2, P.ee2_b, s_w3, P.ee3_b,
                 h1_0, h1_1, h2_0, h2_1, yb0, yb1, agg0, agg1,
                 s_ii, s_jj, s_jl, tid);

    // ---- ne MLP ----
    layer2<64, false, false>(agg0, agg1, P.ne1_w + 512 * 64, P.ne1_b, ya0, ya1, tid);
    {
        float acc[2][4];
#pragma unroll
        for (int j = 0; j < 4; j++) {
            acc[0][j] = ya0[r * 64 + c0 + j];   // own cells
            acc[1][j] = ya1[r * 64 + c0 + j];
        }
#pragma unroll 1
        for (int ch = 0; ch < 8; ch++) {
            for (int idx = tid; idx < 2048; idx += NT) {
                int o = idx >> 6, fl = idx & 63;
                int t = 2 * ch + (fl >> 5), e = fl & 31;
                int off = (t * 32 + o) * 32 + e;
                float v0 = zb0[off], v1 = zb1[off];
                if (t > 0) {
                    int om = off - 1024;
                    v0 -= zb0[om]; v1 -= zb1[om];
                }
                h1_0[o * 64 + fl] = v0;
                h1_1[o * 64 + fl] = v1;
            }
            __syncthreads();
            acc_chunk2(h1_0, h1_1, P.ne1_w + ch * 4096, acc, r, c0);
            __syncthreads();
        }
#pragma unroll
        for (int j = 0; j < 4; j++) {
            ya0[r * 64 + c0 + j] = fmaxf(acc[0][j], 0.f);
            ya1[r * 64 + c0 + j] = fmaxf(acc[1][j], 0.f);
        }
    }
    __syncthreads();
    layer2<64, false, true>(ya0, ya1, P.ne2_w, P.ne2_b, h1_0, h1_1, tid);
    __syncthreads();
    layer_small_2(h1_0, h1_1, 64, P.ne3_w, P.ne3_b, h2_0, h2_1, 32, true, tid);
    __syncthreads();
    layer_small_2(h2_0, h2_1, 32, P.ne4_w, P.ne4_b, h1_0, h1_1, 32, false, tid);  // z_impl
    __syncthreads();

    // zc = concat(z[b,-1], z_impl); restage w2/w3 with le weights
    const float* zl0 = zb0 + 15 * 32 * 32;
    const float* zl1 = zb1 + 15 * 32 * 32;
    for (int idx = tid; idx < 2048; idx += NT) {
        int o = idx >> 6, c = idx & 63;
        zc0[idx] = (c < 32) ? zl0[o * 32 + c] : h1_0[o * 32 + (c - 32)];
        zc1[idx] = (c < 32) ? zl1[o * 32 + c] : h1_1[o * 32 + (c - 32)];
    }
    for (int idx = tid; idx < 4096; idx += NT) {
        s_w2[idx] = P.le2_w[idx];
        s_w3[idx] = P.le3_w[idx];
    }
    __syncthreads();

    // ---- rollout ----
    const int ostride = P.t_future * 1024;
    float* out0 = P.out + (size_t)(2 * blockIdx.x) * ostride;
    float* out1 = out0 + ostride;
#pragma unroll 1
    for (int t = 0; t < P.t_future; t++) {
        layer2<64, false, false>(zc0, zc1, s_wle1,           P.le1_b, ya0, ya1, tid);
        layer2<64, false, false>(zc0, zc1, s_wle1 + 64 * 64, nullptr, yb0, yb1, tid);
        __syncthreads();
        edge_block_2(ya0, ya1, yb0, yb1, s_w2, P.le2_b, s_w3, P.le3_b,
                     h1_0, h1_1, h2_0, h2_1, yb0, yb1, agg0, agg1,
                     s_ii, s_jj, s_jl, tid);

        layer2<64, false, false>(zc0, zc1, P.lt1_w,            P.lt1_b, h1_0, h1_1, tid);
        layer2<64, true,  true >(agg0, agg1, P.lt1_w + 64 * 64, nullptr, h1_0, h1_1, tid);
        __syncthreads();
        layer2<64, false, true>(h1_0, h1_1, P.lt2_w, P.lt2_b, h2_0, h2_1, tid);
        __syncthreads();
        layer_small_2(h2_0, h2_1, 64, P.lt3_w, P.lt3_b, h1_0, h1_1, 32, true, tid);
        __syncthreads();
        layer_small_2(h1_0, h1_1, 32, P.lt4_w, P.lt4_b, h2_0, h2_1, 16, true, tid);
        __syncthreads();
        layer2<16, false, false>(h2_0, h2_1, P.lt5_w, P.lt5_b, h1_0, h1_1, tid);  // delta
        __syncthreads();

        for (int idx = tid; idx < 2048; idx += NT) {
            float zn0 = zc0[idx] + h1_0[idx];
            float zn1 = zc1[idx] + h1_1[idx];
            zc0[idx] = zn0; zc1[idx] = zn1;
            int o = idx >> 6, c = idx & 63;
            if (c < 32) {
                out0[t * 1024 + o * 32 + c] = zn0;
                out1[t * 1024 + o * 32 + c] = zn1;
            }
        }
        __syncthreads();
    }
}

extern "C" void kernel_launch(void* const* d_in, const int* in_sizes, int n_in,
                              void* d_out, int out_size)
{
    Params P;
    int i = 0;
    P.z     = (const float*)d_in[i++];
    P.ee1_w = (const float*)d_in[i++]; P.ee1_b = (const float*)d_in[i++];
    P.ee2_w = (const float*)d_in[i++]; P.ee2_b = (const float*)d_in[i++];
    P.ee3_w = (const float*)d_in[i++]; P.ee3_b = (const float*)d_in[i++];
    P.ne1_w = (const float*)d_in[i++]; P.ne1_b = (const float*)d_in[i++];
    P.ne2_w = (const float*)d_in[i++]; P.ne2_b = (const float*)d_in[i++];
    P.ne3_w = (const float*)d_in[i++]; P.ne3_b = (const float*)d_in[i++];
    P.ne4_w = (const float*)d_in[i++]; P.ne4_b = (const float*)d_in[i++];
    P.le1_w = (const float*)d_in[i++]; P.le1_b = (const float*)d_in[i++];
    P.le2_w = (const float*)d_in[i++]; P.le2_b = (const float*)d_in[i++];
    P.le3_w = (const float*)d_in[i++]; P.le3_b = (const float*)d_in[i++];
    P.lt1_w = (const float*)d_in[i++]; P.lt1_b = (const float*)d_in[i++];
    P.lt2_w = (const float*)d_in[i++]; P.lt2_b = (const float*)d_in[i++];
    P.lt3_w = (const float*)d_in[i++]; P.lt3_b = (const float*)d_in[i++];
    P.lt4_w = (const float*)d_in[i++]; P.lt4_b = (const float*)d_in[i++];
    P.lt5_w = (const float*)d_in[i++]; P.lt5_b = (const float*)d_in[i++];
    P.out = (float*)d_out;
    P.t_future = out_size / (256 * 32 * 32);

    cudaFuncSetAttribute(RelationalLatentDynamics_82849919140105_kernel,
                         cudaFuncAttributeMaxDynamicSharedMemorySize, SMEM_BYTES);
    RelationalLatentDynamics_82849919140105_kernel<<<128, NT, SMEM_BYTES>>>(P);
}